// round 13
// baseline (speedup 1.0000x reference)
#include <cuda_runtime.h>
#include <cuda_fp16.h>
#include <cstdint>

// ---------------------------------------------------------------------------
// Problem constants
// ---------------------------------------------------------------------------
#define BATCH 16
#define DDIM  1024
#define NMAX  8192
#define MTOT  (BATCH * NMAX)     // 131072 rows
#define MT    1024               // M tiles of 128 rows
#define NT2   16                 // N sub-tiles of 64 cols

// fp32 constants mirroring the reference's fp32 math
#define TWO_PI_F 6.28318548202514648438f
#define PI2_HI   6.28318548202514648438f
#define PI2_LO  -1.74845553e-7f
#define INV_2PI  0.15915494309189535f

// W images: 8 x 32KB (128 d-rows x 128 fp16 each, swizzled 256B rows) = 256KB.
// A 64-row subtile j (j=0..15) is the contiguous 16KB chunk at g_B + j*16384.
__device__ __align__(1024) static unsigned char g_B[(size_t)8 * 32768];

// ---------------------------------------------------------------------------
// Helpers
// ---------------------------------------------------------------------------
__device__ __forceinline__ uint32_t smem_u32(const void* p) {
    uint32_t a;
    asm("{ .reg .u64 t; cvta.to.shared.u64 t, %1; cvt.u32.u64 %0, t; }" : "=r"(a) : "l"(p));
    return a;
}

__device__ __forceinline__ unsigned sw(unsigned row, unsigned kb) {
    return row * 256u + (kb ^ ((row & 7u) << 4));
}

__device__ __forceinline__ unsigned packh2(__half a, __half b) {
    return (unsigned)__half_as_ushort(a) | ((unsigned)__half_as_ushort(b) << 16);
}

#define CP_ASYNC16(sm, gp) \
    asm volatile("cp.async.cg.shared.global [%0], [%1], 16;" :: "r"(sm), "l"(gp))
#define CP_ASYNC_COMMIT() asm volatile("cp.async.commit_group;" ::: "memory")
#define CP_ASYNC_WAIT0()  asm volatile("cp.async.wait_group 0;" ::: "memory")

#define LDSM_X4(r, addr) \
    asm volatile("ldmatrix.sync.aligned.m8n8.x4.shared.b16 {%0,%1,%2,%3}, [%4];" \
        : "=r"((r)[0]), "=r"((r)[1]), "=r"((r)[2]), "=r"((r)[3]) : "r"(addr))

#define MMA16816(c, a, b0v, b1v) \
    asm volatile("mma.sync.aligned.m16n8k16.row.col.f32.f16.f16.f32 " \
        "{%0,%1,%2,%3}, {%4,%5,%6,%7}, {%8,%9}, {%0,%1,%2,%3};" \
        : "+f"((c)[0]), "+f"((c)[1]), "+f"((c)[2]), "+f"((c)[3]) \
        : "r"((a)[0]), "r"((a)[1]), "r"((a)[2]), "r"((a)[3]), "r"(b0v), "r"(b1v))

#define STG_CS_V4F(ptr, a, bb, c, d) \
    asm volatile("st.global.cs.v4.f32 [%0], {%1, %2, %3, %4};" \
        :: "l"(ptr), "f"(a), "f"(bb), "f"(c), "f"(d) : "memory")
#define STG_CS_V4Z(ptr) \
    asm volatile("st.global.cs.v4.b32 [%0], {%1, %1, %1, %1};" :: "l"(ptr), "r"(0u) : "memory")

// Butterfly stage over NS float2 slots: swap lane-bit K with slot-bit M.
template<int K, int M, int NS>
__device__ __forceinline__ void xstage(float2* v, int lane) {
    const bool hi = ((lane >> K) & 1) != 0;
    #pragma unroll
    for (int i0 = 0; i0 < NS; ++i0) {
        if (i0 & (1 << M)) continue;
        const int i1 = i0 | (1 << M);
        float sx = hi ? v[i0].x : v[i1].x;
        float sy = hi ? v[i0].y : v[i1].y;
        float rx = __shfl_xor_sync(0xffffffffu, sx, 1 << K);
        float ry = __shfl_xor_sync(0xffffffffu, sy, 1 << K);
        if (hi) { v[i0].x = rx; v[i0].y = ry; }
        else    { v[i1].x = rx; v[i1].y = ry; }
    }
}

// ---------------------------------------------------------------------------
// W prep: W[1024,128] fp32 -> fp16, swizzled tile images (unchanged layout)
// ---------------------------------------------------------------------------
__global__ void __launch_bounds__(256) wprep_kernel(const float* __restrict__ W)
{
    int idx  = blockIdx.x * 256 + threadIdx.x;     // < 8*128*16 = 16384
    int nt   = idx >> 11;
    int rem  = idx & 2047;
    int drow = rem >> 4;
    int kg   = rem & 15;

    const float* wr = W + (size_t)(nt * 128 + drow) * 128 + kg * 8;
    unsigned hi[4];
    #pragma unroll
    for (int j = 0; j < 4; ++j)
        hi[j] = packh2(__float2half_rn(wr[2 * j]), __float2half_rn(wr[2 * j + 1]));
    unsigned char* base = g_B + (size_t)nt * 32768;
    *reinterpret_cast<uint4*>(base + sw((unsigned)drow, (unsigned)kg * 16)) =
        make_uint4(hi[0], hi[1], hi[2], hi[3]);
}

// ---------------------------------------------------------------------------
// Fused gen + GEMM (+ mask tail). Single-pass fp16. 3 CTAs/SM (64KB smem, <=84 regs).
// CTA tile 128 x 64; warp tile 32 x 32; 16 N-iterations, phase-staggered.
// smem: A [0,32K), B buf0 [32K,48K), B buf1 [48K,64K)
// ---------------------------------------------------------------------------
#define SMEM_A     0
#define SMEM_B     32768
#define SMEM_TOTAL 65536

__global__ void __launch_bounds__(256, 3)
gemm_kernel(const int* __restrict__ lengths, float* __restrict__ out,
            float* __restrict__ mask_out)
{
    extern __shared__ unsigned char smem[];
    const uint32_t sb = smem_u32(smem);
    const int tid  = threadIdx.x;
    const int lane = tid & 31;
    const int wid  = tid >> 5;

    const int mtile = blockIdx.x;          // 0..1023
    const int b     = mtile >> 6;
    const int n0    = (mtile & 63) * 128;
    const int phase = mtile & 15;          // co-resident CTAs differ by 4/8 (148,296 mod 16)

    const int   L  = lengths[b];
    const float Lf = (float)L;

    // ---- Mask tail for this tile's 128 rows (fused) ----
    if (mask_out != nullptr && tid < 128) {
        int n = n0 + tid;
        mask_out[(size_t)mtile * 128 + tid] = (n < L) ? 1.0f : 0.0f;
    }

    // ---- Fast path: fully-masked tile -> pure zero fill ----
    if (n0 >= L) {
        float* base = out + (size_t)mtile * 128 * DDIM;
        #pragma unroll 4
        for (int i = tid; i < (128 * DDIM) / 4; i += 256)
            STG_CS_V4Z(base + (size_t)i * 4);
        return;
    }

    // ---- Prologue: async-copy first B subtile (16KB) ----
    {
        const unsigned char* gB0 = g_B + (size_t)phase * 16384;
        #pragma unroll
        for (int it = 0; it < 4; ++it)
            CP_ASYNC16(sb + SMEM_B + it * 4096 + tid * 16, gB0 + it * 4096 + tid * 16);
        CP_ASYNC_COMMIT();
    }

    // ---- Generate feats tile (fp16, masked, swizzled) via rotation recurrence ----
    {
        const int row0 = tid >> 4;         // 0..15
        const int kg   = tid & 15;
        const float nf = (float)(n0 + row0);

        float c[4], s[4], C[4], S[4];
        #pragma unroll
        for (int j = 0; j < 4; ++j) {
            int k = kg * 4 + j + 1;
            float Delta = (TWO_PI_F * (float)k) / Lf;
            float theta = nf * Delta;
            float q = rintf(theta * INV_2PI);
            float r = fmaf(-q, PI2_HI, theta);
            r       = fmaf(-q, PI2_LO, r);
            __sincosf(r, &s[j], &c[j]);
            __sincosf(16.0f * Delta, &S[j], &C[j]);
        }

        #pragma unroll
        for (int it = 0; it < 8; ++it) {
            int row = row0 + it * 16;
            int n   = n0 + row;
            float m = (n < L) ? 0.125f : 0.0f;
            unsigned hi[4];
            #pragma unroll
            for (int j = 0; j < 4; ++j)
                hi[j] = packh2(__float2half_rn(c[j] * m), __float2half_rn(s[j] * m));
            *reinterpret_cast<uint4*>(smem + SMEM_A + sw((unsigned)row, (unsigned)kg * 16)) =
                make_uint4(hi[0], hi[1], hi[2], hi[3]);
            #pragma unroll
            for (int j = 0; j < 4; ++j) {
                float cn = fmaf(c[j], C[j], -s[j] * S[j]);
                float sn = fmaf(s[j], C[j],  c[j] * S[j]);
                c[j] = cn; s[j] = sn;
            }
        }
    }

    // ---- Per-thread ldmatrix address components (warp tile 32 rows x 32 cols) ----
    const unsigned m0 = (unsigned)(wid >> 1) * 32u;   // warp M base (0,32,64,96)
    const unsigned nb = (unsigned)(wid & 1) * 32u;    // warp N base within 64-col tile
    const unsigned aRow  = m0 + (unsigned)(lane & 15);
    const unsigned aXr   = (aRow & 7u) << 4;
    const unsigned aC0   = (unsigned)(lane & 16);
    const uint32_t aBase0 = sb + SMEM_A + aRow * 256u;
    const uint32_t aBase1 = aBase0 + 16u * 256u;
    const unsigned bRl = (unsigned)((lane & 7) + ((lane & 16) ? 8 : 0));
    const unsigned bXr = (bRl & 7u) << 4;
    const unsigned bC0 = (unsigned)((lane & 8) ? 16 : 0);

    __syncthreads();   // A tile ready

    for (int it = 0; it < NT2; ++it) {
        const int nt = (it + phase) & 15;  // actual 64-col subtile index

        CP_ASYNC_WAIT0();
        __syncthreads();   // B subtile ready; all warps done with the other buffer

        if (it + 1 < NT2) {
            const unsigned char* gBn = g_B + (size_t)(((it + 1 + phase) & 15)) * 16384;
            uint32_t bo = sb + SMEM_B + (unsigned)((it + 1) & 1) * 16384u;
            #pragma unroll
            for (int i2 = 0; i2 < 4; ++i2)
                CP_ASYNC16(bo + i2 * 4096 + tid * 16, gBn + i2 * 4096 + tid * 16);
            CP_ASYNC_COMMIT();
        }

        const uint32_t bBase = sb + SMEM_B + (unsigned)(it & 1) * 16384u;

        // acc[0..3]: m-frag 0 (rows m0+q, m0+8+q), acc[4..7]: m-frag 1 (rows +16).
        // acc[4h+i] covers cols [8i, 8i+8) of the warp's 32-col region.
        float acc[8][4];
        #pragma unroll
        for (int i = 0; i < 8; ++i)
            #pragma unroll
            for (int j = 0; j < 4; ++j) acc[i][j] = 0.0f;

        #pragma unroll
        for (int ks = 0; ks < 8; ++ks) {
            const unsigned akb = ((unsigned)ks * 32u + aC0) ^ aXr;
            uint32_t a0[4], a1[4];
            LDSM_X4(a0, aBase0 + akb);
            LDSM_X4(a1, aBase1 + akb);

            const unsigned bkb = ((unsigned)ks * 32u + bC0) ^ bXr;
            #pragma unroll
            for (int np = 0; np < 2; ++np) {
                uint32_t bh[4];
                LDSM_X4(bh, bBase + (nb + np * 16u + bRl) * 256u + bkb);
                MMA16816(acc[np * 2],         a0, bh[0], bh[1]);
                MMA16816(acc[np * 2 + 1],     a0, bh[2], bh[3]);
                MMA16816(acc[4 + np * 2],     a1, bh[0], bh[1]);
                MMA16816(acc[4 + np * 2 + 1], a1, bh[2], bh[3]);
            }
        }

        // ---- Epilogue: 4-slot butterfly -> STG.128 (4 consecutive cols/lane) ----
        // Rows: m0 + 16h + 8ss + q (q = lane>>2). After the 2 stages, lane lam
        // (=lane&3) slot tau holds cols 16*(tau>>1) + 4*lam + 2*(tau&1) +{0,1}.
        {
            const int q   = lane >> 2;
            const int lam = lane & 3;
            const size_t rowbase = ((size_t)(mtile * 128) + m0) * DDIM
                                 + (size_t)nt * 64 + nb + 4 * lam;
            #pragma unroll
            for (int h = 0; h < 2; ++h) {
                #pragma unroll
                for (int ssv = 0; ssv < 2; ++ssv) {
                    float2 v[4];
                    #pragma unroll
                    for (int t = 0; t < 4; ++t) {
                        v[t].x = acc[4 * h + t][2 * ssv];
                        v[t].y = acc[4 * h + t][2 * ssv + 1];
                    }
                    xstage<1, 0, 4>(v, lane);
                    xstage<0, 0, 4>(v, lane);
                    float* rp = out + rowbase + (size_t)(16 * h + 8 * ssv + q) * DDIM;
                    #pragma unroll
                    for (int g = 0; g < 2; ++g)
                        STG_CS_V4F(rp + 16 * g,
                                   v[2 * g].x, v[2 * g].y,
                                   v[2 * g + 1].x, v[2 * g + 1].y);
                }
            }
        }
    }
}

// ---------------------------------------------------------------------------
extern "C" void kernel_launch(void* const* d_in, const int* in_sizes, int n_in,
                              void* d_out, int out_size)
{
    const int*   lengths = (const int*)d_in[0];
    const float* W       = (const float*)d_in[1];
    float*       out     = (float*)d_out;
    (void)in_sizes; (void)n_in;

    cudaFuncSetAttribute(gemm_kernel,
                         cudaFuncAttributeMaxDynamicSharedMemorySize, SMEM_TOTAL);

    long long pos_elems = (long long)MTOT * DDIM;
    float* mask_ptr = ((long long)out_size >= pos_elems + (long long)MTOT)
                          ? (out + pos_elems) : nullptr;

    wprep_kernel<<<64, 256>>>(W);
    gemm_kernel<<<MT, 256, SMEM_TOTAL>>>(lengths, out, mask_ptr);
}